// round 1
// baseline (speedup 1.0000x reference)
#include <cuda_runtime.h>
#include <cuda_bf16.h>
#include <cstdint>

// Problem constants
#define B_   256
#define NV_  196
#define LT_  32
#define CI_  768
#define CT_  512
#define NROWS (B_*NV_)      // 50176
#define KVROWS (B_*LT_)     // 8192

// -------- scratch (no allocation allowed -> __device__ globals) --------
__device__ float g_q[(size_t)NROWS * CI_];
__device__ float g_k[(size_t)KVROWS * CI_];
__device__ float g_v[(size_t)KVROWS * CI_];
__device__ float g_fused[(size_t)NROWS * CI_];
__device__ float g_h[(size_t)NROWS * CI_];

// -------- packed f32x2 helpers (FFMA2 path, 2x fp32 throughput) --------
__device__ __forceinline__ unsigned long long pk2(float lo, float hi) {
    unsigned long long r;
    asm("mov.b64 %0, {%1, %2};" : "=l"(r) : "f"(lo), "f"(hi));
    return r;
}
__device__ __forceinline__ unsigned long long pkdup(float x) {
    unsigned long long r;
    asm("mov.b64 %0, {%1, %1};" : "=l"(r) : "f"(x));
    return r;
}
__device__ __forceinline__ unsigned long long ffma2(unsigned long long a,
                                                    unsigned long long b,
                                                    unsigned long long c) {
    unsigned long long d;
    asm("fma.rn.f32x2 %0, %1, %2, %3;" : "=l"(d) : "l"(a), "l"(b), "l"(c));
    return d;
}
__device__ __forceinline__ void upk2(unsigned long long v, float& lo, float& hi) {
    asm("mov.b64 {%0, %1}, %2;" : "=f"(lo), "=f"(hi) : "l"(v));
}

__device__ __forceinline__ float qgelu(float x) {
    return x / (1.0f + __expf(-1.702f * x));
}

// ---------------- tiled GEMM: C[M,768] = A[M,K] @ B[K,768] + bias (opt gelu) ----
// BM=BN=128, BK=16, 256 threads, 8x8 per thread, FFMA2 accumulators.
template<int DO_GELU>
__global__ __launch_bounds__(256, 2)
void gemm_kernel(const float* __restrict__ A, const float* __restrict__ Bm,
                 const float* __restrict__ bias, float* __restrict__ C,
                 int M, int K) {
    const int N = 768;
    __shared__ float As[16][128];   // [k][m]
    __shared__ float Bs[16][128];   // [k][n]

    int bx = blockIdx.x;            // N tile (0..5)
    int by = blockIdx.y;            // M tile
    int tid = threadIdx.x;
    int tx = tid & 15;
    int ty = tid >> 4;

    unsigned long long acc[8][4];
#pragma unroll
    for (int i = 0; i < 8; i++)
#pragma unroll
        for (int j = 0; j < 4; j++) acc[i][j] = 0ull;

    const float* Ablk = A + (size_t)by * 128 * K;
    const float* Bblk = Bm + bx * 128;

    for (int k0 = 0; k0 < K; k0 += 16) {
        // load A tile 128x16 (transpose into As[k][m]); 512 float4, 2 per thread
#pragma unroll
        for (int s = 0; s < 2; s++) {
            int id = tid * 2 + s;
            int row = id >> 2, c4 = id & 3;
            float4 v = *(const float4*)(Ablk + (size_t)row * K + k0 + c4 * 4);
            As[c4 * 4 + 0][row] = v.x;
            As[c4 * 4 + 1][row] = v.y;
            As[c4 * 4 + 2][row] = v.z;
            As[c4 * 4 + 3][row] = v.w;
        }
        // load B tile 16x128; 512 float4, 2 per thread
#pragma unroll
        for (int s = 0; s < 2; s++) {
            int id = tid * 2 + s;
            int r = id >> 5, c4 = id & 31;
            *(float4*)&Bs[r][c4 * 4] = *(const float4*)(Bblk + (size_t)(k0 + r) * N + c4 * 4);
        }
        __syncthreads();
#pragma unroll
        for (int kk = 0; kk < 16; kk++) {
            float4 a0 = *(const float4*)&As[kk][ty * 8];
            float4 a1 = *(const float4*)&As[kk][ty * 8 + 4];
            float4 b0 = *(const float4*)&Bs[kk][tx * 8];
            float4 b1 = *(const float4*)&Bs[kk][tx * 8 + 4];
            unsigned long long bp[4];
            bp[0] = pk2(b0.x, b0.y);
            bp[1] = pk2(b0.z, b0.w);
            bp[2] = pk2(b1.x, b1.y);
            bp[3] = pk2(b1.z, b1.w);
            float av[8] = {a0.x, a0.y, a0.z, a0.w, a1.x, a1.y, a1.z, a1.w};
#pragma unroll
            for (int i = 0; i < 8; i++) {
                unsigned long long ap = pkdup(av[i]);
#pragma unroll
                for (int j = 0; j < 4; j++)
                    acc[i][j] = ffma2(ap, bp[j], acc[i][j]);
            }
        }
        __syncthreads();
    }

    // epilogue
    int cbase = bx * 128 + tx * 8;
    float bv[8];
#pragma unroll
    for (int j = 0; j < 8; j++) bv[j] = bias[cbase + j];
#pragma unroll
    for (int i = 0; i < 8; i++) {
        int row = by * 128 + ty * 8 + i;
        float o[8];
#pragma unroll
        for (int j2 = 0; j2 < 4; j2++) upk2(acc[i][j2], o[2 * j2], o[2 * j2 + 1]);
#pragma unroll
        for (int j = 0; j < 8; j++) {
            o[j] += bv[j];
            if (DO_GELU) o[j] = qgelu(o[j]);
        }
        float* cp = C + (size_t)row * N + cbase;
        *(float4*)cp       = make_float4(o[0], o[1], o[2], o[3]);
        *(float4*)(cp + 4) = make_float4(o[4], o[5], o[6], o[7]);
    }
}

// ---------------- attention: per (b,h) block; softmax over Lt=32 ----------------
// fused[b*196+n, h*64+d] = sum_l softmax(q.k/8)[l] * v[l,d] + vis[b,n,h*64+d]
__global__ __launch_bounds__(256)
void attn_kernel(const float* __restrict__ q_s, const float* __restrict__ k_s,
                 const float* __restrict__ v_s, const float* __restrict__ vis,
                 float* __restrict__ fused) {
    int h = blockIdx.x;   // 0..11
    int b = blockIdx.y;   // 0..255
    __shared__ float4 ksm[32][16];
    __shared__ float4 vsm[32][16];
    int tid = threadIdx.x;

    const float* kbase = k_s + (size_t)b * 32 * 768 + h * 64;
    const float* vbase = v_s + (size_t)b * 32 * 768 + h * 64;
    for (int i = tid; i < 512; i += 256) {
        int l = i >> 4, d4 = i & 15;
        ksm[l][d4] = *(const float4*)(kbase + (size_t)l * 768 + d4 * 4);
        vsm[l][d4] = *(const float4*)(vbase + (size_t)l * 768 + d4 * 4);
    }
    __syncthreads();

    int n = tid;
    if (n < 196) {
        size_t rowoff = (size_t)(b * 196 + n) * 768 + h * 64;
        const float4* qrow = (const float4*)(q_s + rowoff);
        float4 q4[16];
#pragma unroll
        for (int d = 0; d < 16; d++) q4[d] = qrow[d];

        float s[32];
#pragma unroll
        for (int l = 0; l < 32; l++) {
            float ax = 0.f, ay = 0.f, az = 0.f, aw = 0.f;
#pragma unroll
            for (int d = 0; d < 16; d++) {
                float4 kk = ksm[l][d];
                ax += q4[d].x * kk.x;
                ay += q4[d].y * kk.y;
                az += q4[d].z * kk.z;
                aw += q4[d].w * kk.w;
            }
            s[l] = (ax + ay + az + aw) * 0.125f;
        }
        float m = s[0];
#pragma unroll
        for (int l = 1; l < 32; l++) m = fmaxf(m, s[l]);
        float sum = 0.f;
#pragma unroll
        for (int l = 0; l < 32; l++) { s[l] = __expf(s[l] - m); sum += s[l]; }
        float inv = 1.0f / sum;

        const float4* visrow = (const float4*)(vis + rowoff);
        float4* outrow = (float4*)(fused + rowoff);
        for (int d = 0; d < 16; d++) {
            float ax = 0.f, ay = 0.f, az = 0.f, aw = 0.f;
#pragma unroll
            for (int l = 0; l < 32; l++) {
                float4 vv = vsm[l][d];
                float p = s[l];
                ax += p * vv.x;
                ay += p * vv.y;
                az += p * vv.z;
                aw += p * vv.w;
            }
            float4 r = visrow[d];
            float4 o;
            o.x = ax * inv + r.x;
            o.y = ay * inv + r.y;
            o.z = az * inv + r.z;
            o.w = aw * inv + r.w;
            outrow[d] = o;
        }
    }
}

// ---------------- thin head: logits = h @ W2[768,2] + b2, one warp per row -----
__global__ __launch_bounds__(256)
void logits_kernel(const float* __restrict__ h_s, const float* __restrict__ W2,
                   const float* __restrict__ b2, float* __restrict__ out) {
    int gwarp = (blockIdx.x * blockDim.x + threadIdx.x) >> 5;
    int lane = threadIdx.x & 31;
    if (gwarp >= NROWS) return;
    const float* row = h_s + (size_t)gwarp * 768;
    const float2* w2 = (const float2*)W2;
    float a0 = 0.f, a1 = 0.f;
#pragma unroll
    for (int i = 0; i < 24; i++) {
        int idx = lane + 32 * i;
        float x = row[idx];
        float2 w = w2[idx];
        a0 += x * w.x;
        a1 += x * w.y;
    }
#pragma unroll
    for (int off = 16; off > 0; off >>= 1) {
        a0 += __shfl_xor_sync(0xffffffffu, a0, off);
        a1 += __shfl_xor_sync(0xffffffffu, a1, off);
    }
    if (lane == 0) {
        out[(size_t)gwarp * 2]     = a0 + b2[0];
        out[(size_t)gwarp * 2 + 1] = a1 + b2[1];
    }
}

// rel_BN = attn.mean(-1).mean(1) == 1/Lt exactly (softmax rows sum to 1)
__global__ void fill_rel(float* __restrict__ p) {
    int i = blockIdx.x * blockDim.x + threadIdx.x;
    if (i < NROWS) p[i] = 1.0f / 32.0f;
}

extern "C" void kernel_launch(void* const* d_in, const int* in_sizes, int n_in,
                              void* d_out, int out_size) {
    const float* vis  = (const float*)d_in[0];
    const float* text = (const float*)d_in[1];
    const float* Wq   = (const float*)d_in[2];
    const float* bq   = (const float*)d_in[3];
    const float* Wk   = (const float*)d_in[4];
    const float* bk   = (const float*)d_in[5];
    const float* Wv   = (const float*)d_in[6];
    const float* bv   = (const float*)d_in[7];
    const float* W1   = (const float*)d_in[8];
    const float* b1   = (const float*)d_in[9];
    const float* W2   = (const float*)d_in[10];
    const float* b2   = (const float*)d_in[11];
    float* out = (float*)d_out;

    float *qs, *ks, *vsc, *fs, *hs;
    cudaGetSymbolAddress((void**)&qs,  g_q);
    cudaGetSymbolAddress((void**)&ks,  g_k);
    cudaGetSymbolAddress((void**)&vsc, g_v);
    cudaGetSymbolAddress((void**)&fs,  g_fused);
    cudaGetSymbolAddress((void**)&hs,  g_h);

    dim3 blk(256);
    // K/V projections: [8192,512]@[512,768]
    gemm_kernel<0><<<dim3(6, KVROWS / 128), blk>>>(text, Wk, bk, ks, KVROWS, CT_);
    gemm_kernel<0><<<dim3(6, KVROWS / 128), blk>>>(text, Wv, bv, vsc, KVROWS, CT_);
    // Q projection: [50176,768]@[768,768]
    gemm_kernel<0><<<dim3(6, NROWS / 128), blk>>>(vis, Wq, bq, qs, NROWS, CI_);
    // attention + residual -> fused
    attn_kernel<<<dim3(12, B_), blk>>>(qs, ks, vsc, vis, fs);
    // MLP1 with quick-gelu epilogue
    gemm_kernel<1><<<dim3(6, NROWS / 128), blk>>>(fs, W1, b1, hs, NROWS, CI_);
    // thin W2 head -> logits (first 100352 floats of out)
    logits_kernel<<<(NROWS * 32 + 255) / 256, blk>>>(hs, W2, b2, out);
    // rel_BN constant tail (last 50176 floats)
    fill_rel<<<(NROWS + 255) / 256, blk>>>(out + (size_t)NROWS * 2);
}

// round 3
// speedup vs baseline: 2.0272x; 2.0272x over previous
#include <cuda_runtime.h>
#include <cuda_bf16.h>
#include <cstdint>

// Problem constants
#define B_   256
#define NV_  196
#define LT_  32
#define CI_  768
#define CT_  512
#define NROWS (B_*NV_)      // 50176
#define KVROWS (B_*LT_)     // 8192

// -------------------- scratch (device globals; no allocation) --------------------
__device__ __nv_bfloat16 g_vis_hi [(size_t)NROWS * CI_];
__device__ __nv_bfloat16 g_vis_lo [(size_t)NROWS * CI_];
__device__ __nv_bfloat16 g_text_hi[(size_t)KVROWS * CT_];
__device__ __nv_bfloat16 g_text_lo[(size_t)KVROWS * CT_];
__device__ __nv_bfloat16 g_wqT_hi [(size_t)CI_ * CI_];
__device__ __nv_bfloat16 g_wqT_lo [(size_t)CI_ * CI_];
__device__ __nv_bfloat16 g_wkT_hi [(size_t)CI_ * CT_];
__device__ __nv_bfloat16 g_wkT_lo [(size_t)CI_ * CT_];
__device__ __nv_bfloat16 g_wvT_hi [(size_t)CI_ * CT_];
__device__ __nv_bfloat16 g_wvT_lo [(size_t)CI_ * CT_];
__device__ __nv_bfloat16 g_w1T_hi [(size_t)CI_ * CI_];
__device__ __nv_bfloat16 g_w1T_lo [(size_t)CI_ * CI_];
__device__ __nv_bfloat16 g_fused_hi[(size_t)NROWS * CI_];
__device__ __nv_bfloat16 g_fused_lo[(size_t)NROWS * CI_];
__device__ float g_q[(size_t)NROWS * CI_];
__device__ float g_k[(size_t)KVROWS * CI_];
__device__ float g_v[(size_t)KVROWS * CI_];
__device__ float g_h[(size_t)NROWS * CI_];

// -------------------- small helpers --------------------
__device__ __forceinline__ float qgelu(float x) {
    return x / (1.0f + __expf(-1.702f * x));
}
__device__ __forceinline__ void split_bf(float x, __nv_bfloat16& h, __nv_bfloat16& l) {
    h = __float2bfloat16(x);
    l = __float2bfloat16(x - __bfloat162float(h));
}
__device__ __forceinline__ uint32_t pack_bf2(__nv_bfloat16 a, __nv_bfloat16 b) {
    uint32_t la = (uint32_t)__bfloat16_as_ushort(a);
    uint32_t lb = (uint32_t)__bfloat16_as_ushort(b);
    return la | (lb << 16);
}
__device__ __forceinline__ uint32_t smem_u32(const void* p) {
    uint32_t a;
    asm("{ .reg .u64 t; cvta.to.shared.u64 t, %1; cvt.u32.u64 %0, t; }" : "=r"(a) : "l"(p));
    return a;
}

// -------------------- mma / ldmatrix / cp.async primitives (base sm_103) --------
__device__ __forceinline__ void ldsm_x4(uint32_t* r, uint32_t addr) {
    asm volatile("ldmatrix.sync.aligned.m8n8.x4.shared.b16 {%0,%1,%2,%3}, [%4];"
                 : "=r"(r[0]), "=r"(r[1]), "=r"(r[2]), "=r"(r[3]) : "r"(addr));
}
__device__ __forceinline__ void mma_bf16(float* d, const uint32_t* a, const uint32_t* b) {
    asm volatile(
        "mma.sync.aligned.m16n8k16.row.col.f32.bf16.bf16.f32 "
        "{%0,%1,%2,%3}, {%4,%5,%6,%7}, {%8,%9}, {%0,%1,%2,%3};"
        : "+f"(d[0]), "+f"(d[1]), "+f"(d[2]), "+f"(d[3])
        : "r"(a[0]), "r"(a[1]), "r"(a[2]), "r"(a[3]), "r"(b[0]), "r"(b[1]));
}
__device__ __forceinline__ void cp_async16(uint32_t dst, const void* src) {
    asm volatile("cp.async.ca.shared.global [%0], [%1], 16;" :: "r"(dst), "l"(src));
}
__device__ __forceinline__ void cp_commit() {
    asm volatile("cp.async.commit_group;");
}
__device__ __forceinline__ void cp_wait1() {
    asm volatile("cp.async.wait_group 1;");
}

// -------------------- bf16x3 tensor-core GEMM --------------------
// C[M,768] = (Ahi+Alo) @ (Bhi+Blo)^T + bias (opt gelu).
// A: [M,KDIM] K-major bf16 hi/lo. B: [768,KDIM] K-major bf16 hi/lo (pre-transposed).
// Tile 128x128x32, 256 threads, 3-stage cp.async pipeline.
#define SST 40                      // smem row stride in halfwords (80 bytes)
#define TILE_B (128 * SST * 2)      // 10240 bytes per tile
#define STAGE_B (4 * TILE_B)        // Ah, Al, Bh, Bl
#define GEMM_SMEM (3 * STAGE_B)     // 122880 bytes

__device__ __forceinline__ void issue_tile(uint32_t dst, const __nv_bfloat16* src,
                                           int ld, int tid) {
    // 128 rows x 32 halfwords = 512 16B chunks, 2 per thread
#pragma unroll
    for (int it = 0; it < 2; it++) {
        int id = tid + it * 256;
        int r = id >> 2, c = id & 3;
        cp_async16(dst + r * (SST * 2) + c * 16, src + (size_t)r * ld + c * 8);
    }
}

template<int KDIM, int DO_GELU>
__global__ __launch_bounds__(256, 1)
void gemm_mma(const __nv_bfloat16* __restrict__ Ahi, const __nv_bfloat16* __restrict__ Alo,
              const __nv_bfloat16* __restrict__ Bhi, const __nv_bfloat16* __restrict__ Blo,
              const float* __restrict__ bias, float* __restrict__ C) {
    extern __shared__ char smem[];
    const int tid = threadIdx.x;
    const int lane = tid & 31;
    const int wid = tid >> 5;
    const int wm = wid & 3;          // 4 warps along M
    const int wn = wid >> 2;         // 2 warps along N
    const int n0 = blockIdx.x * 128;
    const int m0 = blockIdx.y * 128;

    const uint32_t sbase = smem_u32(smem);

    const __nv_bfloat16* Ah = Ahi + (size_t)m0 * KDIM;
    const __nv_bfloat16* Al = Alo + (size_t)m0 * KDIM;
    const __nv_bfloat16* Bh = Bhi + (size_t)n0 * KDIM;
    const __nv_bfloat16* Bl = Blo + (size_t)n0 * KDIM;

    constexpr int NC = KDIM / 32;

    float acc[2][8][4];
#pragma unroll
    for (int i = 0; i < 2; i++)
#pragma unroll
        for (int j = 0; j < 8; j++)
#pragma unroll
            for (int k = 0; k < 4; k++) acc[i][j][k] = 0.f;

    // prologue: stages 0, 1
#pragma unroll
    for (int p = 0; p < 2; p++) {
        uint32_t st = sbase + p * STAGE_B;
        issue_tile(st,              Ah + p * 32, KDIM, tid);
        issue_tile(st + TILE_B,     Al + p * 32, KDIM, tid);
        issue_tile(st + 2 * TILE_B, Bh + p * 32, KDIM, tid);
        issue_tile(st + 3 * TILE_B, Bl + p * 32, KDIM, tid);
        cp_commit();
    }

    // per-thread fragment address components (byte offsets within a tile)
    // A: row = wm*32 + mi*16 + (lane&15), col_hw = ks*16 + ((lane>>4)<<3)
    const int a_row = wm * 32 + (lane & 15);
    const int a_colb = ((lane >> 4) << 3) * 2;
    // B: n = wn*64 + ni2*16 + (lane&7) + ((lane>>4)<<3), k_hw = ks*16 + (((lane>>3)&1)<<3)
    const int b_row = wn * 64 + (lane & 7) + ((lane >> 4) << 3);
    const int b_colb = (((lane >> 3) & 1) << 3) * 2;

    for (int c = 0; c < NC; c++) {
        cp_wait1();
        __syncthreads();
        // prefetch chunk c+2 into the stage freed at iter c-1
        if (c + 2 < NC) {
            uint32_t st = sbase + ((c + 2) % 3) * STAGE_B;
            int k0 = (c + 2) * 32;
            issue_tile(st,              Ah + k0, KDIM, tid);
            issue_tile(st + TILE_B,     Al + k0, KDIM, tid);
            issue_tile(st + 2 * TILE_B, Bh + k0, KDIM, tid);
            issue_tile(st + 3 * TILE_B, Bl + k0, KDIM, tid);
        }
        cp_commit();

        uint32_t st = sbase + (c % 3) * STAGE_B;
#pragma unroll
        for (int ks = 0; ks < 2; ks++) {
            const int kb = ks * 32;  // 16 halfwords = 32 bytes
            uint32_t Ahf[2][4], Alf[2][4];
#pragma unroll
            for (int mi = 0; mi < 2; mi++) {
                uint32_t arow = (a_row + mi * 16) * (SST * 2) + kb + a_colb;
                ldsm_x4(Ahf[mi], st + arow);
                ldsm_x4(Alf[mi], st + TILE_B + arow);
            }
            uint32_t Bhf[4][4], Blf[4][4];
#pragma unroll
            for (int ni2 = 0; ni2 < 4; ni2++) {
                uint32_t brow = (b_row + ni2 * 16) * (SST * 2) + kb + b_colb;
                ldsm_x4(Bhf[ni2], st + 2 * TILE_B + brow);
                ldsm_x4(Blf[ni2], st + 3 * TILE_B + brow);
            }
#pragma unroll
            for (int mi = 0; mi < 2; mi++)
#pragma unroll
                for (int ni = 0; ni < 8; ni++) {
                    const int ni2 = ni >> 1, od = (ni & 1) * 2;
                    mma_bf16(acc[mi][ni], Ahf[mi], &Bhf[ni2][od]);
                    mma_bf16(acc[mi][ni], Ahf[mi], &Blf[ni2][od]);
                    mma_bf16(acc[mi][ni], Alf[mi], &Bhf[ni2][od]);
                }
        }
        __syncthreads();
    }

    // epilogue
#pragma unroll
    for (int mi = 0; mi < 2; mi++) {
        int row0 = m0 + wm * 32 + mi * 16 + (lane >> 2);
#pragma unroll
        for (int ni = 0; ni < 8; ni++) {
            int col = n0 + wn * 64 + ni * 8 + (lane & 3) * 2;
            float b0 = bias[col], b1 = bias[col + 1];
            float v0 = acc[mi][ni][0] + b0;
            float v1 = acc[mi][ni][1] + b1;
            float v2 = acc[mi][ni][2] + b0;
            float v3 = acc[mi][ni][3] + b1;
            if (DO_GELU) {
                v0 = qgelu(v0); v1 = qgelu(v1); v2 = qgelu(v2); v3 = qgelu(v3);
            }
            *(float2*)(C + (size_t)row0 * 768 + col)       = make_float2(v0, v1);
            *(float2*)(C + (size_t)(row0 + 8) * 768 + col) = make_float2(v2, v3);
        }
    }
}

// -------------------- elementwise fp32 -> bf16 hi/lo split --------------------
__global__ __launch_bounds__(256)
void split_kernel(const float* __restrict__ x, __nv_bfloat16* __restrict__ hi,
                  __nv_bfloat16* __restrict__ lo, int n4) {
    int i = blockIdx.x * blockDim.x + threadIdx.x;
    if (i >= n4) return;
    float4 v = ((const float4*)x)[i];
    __nv_bfloat16 h0, h1, h2, h3, l0, l1, l2, l3;
    split_bf(v.x, h0, l0);
    split_bf(v.y, h1, l1);
    split_bf(v.z, h2, l2);
    split_bf(v.w, h3, l3);
    ((uint2*)hi)[i] = make_uint2(pack_bf2(h0, h1), pack_bf2(h2, h3));
    ((uint2*)lo)[i] = make_uint2(pack_bf2(l0, l1), pack_bf2(l2, l3));
}

// -------------------- weight transpose + split: W[K,N] -> T[N,K] hi/lo --------
__global__ __launch_bounds__(256)
void transpose_split(const float* __restrict__ W, __nv_bfloat16* __restrict__ Thi,
                     __nv_bfloat16* __restrict__ Tlo, int K, int N) {
    __shared__ float t[32][33];
    int n0 = blockIdx.x * 32, k0 = blockIdx.y * 32;
    int tx = threadIdx.x & 31, ty = threadIdx.x >> 5;
#pragma unroll
    for (int s = 0; s < 4; s++)
        t[ty + 8 * s][tx] = W[(size_t)(k0 + ty + 8 * s) * N + n0 + tx];
    __syncthreads();
#pragma unroll
    for (int s = 0; s < 4; s++) {
        int n = n0 + ty + 8 * s;
        int k = k0 + tx;
        float v = t[tx][ty + 8 * s];
        __nv_bfloat16 h, l;
        split_bf(v, h, l);
        Thi[(size_t)n * K + k] = h;
        Tlo[(size_t)n * K + k] = l;
    }
}

// -------------------- attention; emits fused hi/lo bf16 --------------------
__global__ __launch_bounds__(256)
void attn_kernel(const float* __restrict__ q_s, const float* __restrict__ k_s,
                 const float* __restrict__ v_s, const float* __restrict__ vis,
                 __nv_bfloat16* __restrict__ f_hi, __nv_bfloat16* __restrict__ f_lo) {
    int h = blockIdx.x;
    int b = blockIdx.y;
    __shared__ float4 ksm[32][16];
    __shared__ float4 vsm[32][16];
    int tid = threadIdx.x;

    const float* kbase = k_s + (size_t)b * 32 * 768 + h * 64;
    const float* vbase = v_s + (size_t)b * 32 * 768 + h * 64;
    for (int i = tid; i < 512; i += 256) {
        int l = i >> 4, d4 = i & 15;
        ksm[l][d4] = *(const float4*)(kbase + (size_t)l * 768 + d4 * 4);
        vsm[l][d4] = *(const float4*)(vbase + (size_t)l * 768 + d4 * 4);
    }
    __syncthreads();

    int n = tid;
    if (n < 196) {
        size_t rowoff = (size_t)(b * 196 + n) * 768 + h * 64;
        const float4* qrow = (const float4*)(q_s + rowoff);
        float4 q4[16];
#pragma unroll
        for (int d = 0; d < 16; d++) q4[d] = qrow[d];

        float s[32];
#pragma unroll
        for (int l = 0; l < 32; l++) {
            float ax = 0.f, ay = 0.f, az = 0.f, aw = 0.f;
#pragma unroll
            for (int d = 0; d < 16; d++) {
                float4 kk = ksm[l][d];
                ax += q4[d].x * kk.x;
                ay += q4[d].y * kk.y;
                az += q4[d].z * kk.z;
                aw += q4[d].w * kk.w;
            }
            s[l] = (ax + ay + az + aw) * 0.125f;
        }
        float m = s[0];
#pragma unroll
        for (int l = 1; l < 32; l++) m = fmaxf(m, s[l]);
        float sum = 0.f;
#pragma unroll
        for (int l = 0; l < 32; l++) { s[l] = __expf(s[l] - m); sum += s[l]; }
        float inv = 1.0f / sum;

        const float4* visrow = (const float4*)(vis + rowoff);
        uint2* hrow = (uint2*)(f_hi + rowoff);
        uint2* lrow = (uint2*)(f_lo + rowoff);
        for (int d = 0; d < 16; d++) {
            float ax = 0.f, ay = 0.f, az = 0.f, aw = 0.f;
#pragma unroll
            for (int l = 0; l < 32; l++) {
                float4 vv = vsm[l][d];
                float p = s[l];
                ax += p * vv.x;
                ay += p * vv.y;
                az += p * vv.z;
                aw += p * vv.w;
            }
            float4 r = visrow[d];
            float o0 = ax * inv + r.x;
            float o1 = ay * inv + r.y;
            float o2 = az * inv + r.z;
            float o3 = aw * inv + r.w;
            __nv_bfloat16 h0, h1, h2, h3, l0, l1, l2, l3;
            split_bf(o0, h0, l0);
            split_bf(o1, h1, l1);
            split_bf(o2, h2, l2);
            split_bf(o3, h3, l3);
            hrow[d] = make_uint2(pack_bf2(h0, h1), pack_bf2(h2, h3));
            lrow[d] = make_uint2(pack_bf2(l0, l1), pack_bf2(l2, l3));
        }
    }
}

// -------------------- thin head: logits = h @ W2[768,2] + b2 --------------------
__global__ __launch_bounds__(256)
void logits_kernel(const float* __restrict__ h_s, const float* __restrict__ W2,
                   const float* __restrict__ b2, float* __restrict__ out) {
    int gwarp = (blockIdx.x * blockDim.x + threadIdx.x) >> 5;
    int lane = threadIdx.x & 31;
    if (gwarp >= NROWS) return;
    const float* row = h_s + (size_t)gwarp * 768;
    const float2* w2 = (const float2*)W2;
    float a0 = 0.f, a1 = 0.f;
#pragma unroll
    for (int i = 0; i < 24; i++) {
        int idx = lane + 32 * i;
        float x = row[idx];
        float2 w = w2[idx];
        a0 += x * w.x;
        a1 += x * w.y;
    }
#pragma unroll
    for (int off = 16; off > 0; off >>= 1) {
        a0 += __shfl_xor_sync(0xffffffffu, a0, off);
        a1 += __shfl_xor_sync(0xffffffffu, a1, off);
    }
    if (lane == 0) {
        out[(size_t)gwarp * 2]     = a0 + b2[0];
        out[(size_t)gwarp * 2 + 1] = a1 + b2[1];
    }
}

// rel_BN = attn.mean(-1).mean(1) == 1/Lt exactly (softmax rows sum to 1)
__global__ void fill_rel(float* __restrict__ p) {
    int i = blockIdx.x * blockDim.x + threadIdx.x;
    if (i < NROWS) p[i] = 1.0f / 32.0f;
}

// -------------------- host launch --------------------
extern "C" void kernel_launch(void* const* d_in, const int* in_sizes, int n_in,
                              void* d_out, int out_size) {
    const float* vis  = (const float*)d_in[0];
    const float* text = (const float*)d_in[1];
    const float* Wq   = (const float*)d_in[2];
    const float* bq   = (const float*)d_in[3];
    const float* Wk   = (const float*)d_in[4];
    const float* bk   = (const float*)d_in[5];
    const float* Wv   = (const float*)d_in[6];
    const float* bv   = (const float*)d_in[7];
    const float* W1   = (const float*)d_in[8];
    const float* b1   = (const float*)d_in[9];
    const float* W2   = (const float*)d_in[10];
    const float* b2   = (const float*)d_in[11];
    float* out = (float*)d_out;

    __nv_bfloat16 *vh, *vl, *th, *tl, *wqh, *wql, *wkh, *wkl, *wvh, *wvl, *w1h, *w1l, *fh, *fl;
    float *qs, *ks, *vsc, *hs;
    cudaGetSymbolAddress((void**)&vh,  g_vis_hi);
    cudaGetSymbolAddress((void**)&vl,  g_vis_lo);
    cudaGetSymbolAddress((void**)&th,  g_text_hi);
    cudaGetSymbolAddress((void**)&tl,  g_text_lo);
    cudaGetSymbolAddress((void**)&wqh, g_wqT_hi);
    cudaGetSymbolAddress((void**)&wql, g_wqT_lo);
    cudaGetSymbolAddress((void**)&wkh, g_wkT_hi);
    cudaGetSymbolAddress((void**)&wkl, g_wkT_lo);
    cudaGetSymbolAddress((void**)&wvh, g_wvT_hi);
    cudaGetSymbolAddress((void**)&wvl, g_wvT_lo);
    cudaGetSymbolAddress((void**)&w1h, g_w1T_hi);
    cudaGetSymbolAddress((void**)&w1l, g_w1T_lo);
    cudaGetSymbolAddress((void**)&fh,  g_fused_hi);
    cudaGetSymbolAddress((void**)&fl,  g_fused_lo);
    cudaGetSymbolAddress((void**)&qs,  g_q);
    cudaGetSymbolAddress((void**)&ks,  g_k);
    cudaGetSymbolAddress((void**)&vsc, g_v);
    cudaGetSymbolAddress((void**)&hs,  g_h);

    cudaFuncSetAttribute(gemm_mma<768, 0>, cudaFuncAttributeMaxDynamicSharedMemorySize, GEMM_SMEM);
    cudaFuncSetAttribute(gemm_mma<512, 0>, cudaFuncAttributeMaxDynamicSharedMemorySize, GEMM_SMEM);
    cudaFuncSetAttribute(gemm_mma<768, 1>, cudaFuncAttributeMaxDynamicSharedMemorySize, GEMM_SMEM);

    // input splits
    {
        int n4 = NROWS * CI_ / 4;
        split_kernel<<<(n4 + 255) / 256, 256>>>(vis, vh, vl, n4);
    }
    {
        int n4 = KVROWS * CT_ / 4;
        split_kernel<<<(n4 + 255) / 256, 256>>>(text, th, tl, n4);
    }
    // weight transpose+split (tiny)
    transpose_split<<<dim3(CI_ / 32, CI_ / 32), 256>>>(Wq, wqh, wql, CI_, CI_);
    transpose_split<<<dim3(CI_ / 32, CT_ / 32), 256>>>(Wk, wkh, wkl, CT_, CI_);
    transpose_split<<<dim3(CI_ / 32, CT_ / 32), 256>>>(Wv, wvh, wvl, CT_, CI_);
    transpose_split<<<dim3(CI_ / 32, CI_ / 32), 256>>>(W1, w1h, w1l, CI_, CI_);

    // projections via tensor cores (bf16x3)
    gemm_mma<768, 0><<<dim3(6, NROWS / 128), 256, GEMM_SMEM>>>(vh, vl, wqh, wql, bq, qs);
    gemm_mma<512, 0><<<dim3(6, KVROWS / 128), 256, GEMM_SMEM>>>(th, tl, wkh, wkl, bk, ks);
    gemm_mma<512, 0><<<dim3(6, KVROWS / 128), 256, GEMM_SMEM>>>(th, tl, wvh, wvl, bv, vsc);

    // attention + residual -> fused hi/lo
    attn_kernel<<<dim3(12, B_), 256>>>(qs, ks, vsc, vis, fh, fl);

    // MLP1 with gelu epilogue
    gemm_mma<768, 1><<<dim3(6, NROWS / 128), 256, GEMM_SMEM>>>(fh, fl, w1h, w1l, b1, hs);

    // thin head + rel tail
    logits_kernel<<<(NROWS * 32 + 255) / 256, 256>>>(hs, W2, b2, out);
    fill_rel<<<(NROWS + 255) / 256, 256>>>(out + (size_t)NROWS * 2);
}